// round 15
// baseline (speedup 1.0000x reference)
#include <cuda_runtime.h>
#include <cuda_fp16.h>
#include <cuda_fp8.h>
#include <cstdint>

#define NNODES 50000
#define NEDGES 800000
#define EPSF 1e-7f

// ---------------- static device scratch ----------------
__device__ __align__(16) uint32_t g_u0b [NNODES*64];    // u0 packed f16x2 (128 vals)
__device__ __align__(16) uint32_t g_accb[NNODES*64];    // acc packed f16x2
__device__ __align__(16) uint32_t g_v   [NNODES*192];   // GEMM C packed f16x2 (max 384)
__device__ __align__(16) uint32_t g_bufBb[NNODES*192];  // final ht packed f16x2
__device__ __align__(16) uint32_t g_A8 [NNODES*64];     // A plane e4m3 x4 (max K=256)
__device__ __align__(16) uint32_t g_W0f[128*32];        // W e4m3 x4 (M x K/4)
__device__ __align__(16) uint32_t g_W1f[256*32];
__device__ __align__(16) uint32_t g_W2f[384*64];
__device__ __align__(16) float g_bp0[128];
__device__ __align__(16) float g_bp1[256];
__device__ __align__(16) float g_bp2[384];
__device__ float g_sums[384];

// ---------------- helpers ----------------
__device__ __forceinline__ float warpSum(float v){
#pragma unroll
    for (int o = 16; o > 0; o >>= 1) v += __shfl_xor_sync(0xffffffffu, v, o);
    return v;
}
__device__ __forceinline__ float arcosh_cl(float x){
    x = fmaxf(x, 1.0f + EPSF);
    return logf(x + sqrtf(x * x - 1.0f));
}
__device__ __forceinline__ uint32_t hpack2(float x, float y){
    __half2 h = __floats2half2_rn(x, y);
    return *reinterpret_cast<uint32_t*>(&h);
}
__device__ __forceinline__ void hunpack2(uint32_t p, float& lo, float& hi){
    __half2 h = *reinterpret_cast<__half2*>(&p);
    float2 f = __half22float2(h);
    lo = f.x; hi = f.y;
}
__device__ __forceinline__ uint32_t f8pack4(float a, float b, float c, float d){
    __nv_fp8x2_storage_t lo = __nv_cvt_float2_to_fp8x2(make_float2(a, b), __NV_SATFINITE, __NV_E4M3);
    __nv_fp8x2_storage_t hi = __nv_cvt_float2_to_fp8x2(make_float2(c, d), __NV_SATFINITE, __NV_E4M3);
    return (uint32_t)lo | ((uint32_t)hi << 16);
}
__device__ __forceinline__ void mma_f8(float* c, const uint32_t* a, uint32_t b0, uint32_t b1){
    asm volatile(
        "mma.sync.aligned.m16n8k32.row.col.f32.e4m3.e4m3.f32 "
        "{%0,%1,%2,%3}, {%4,%5,%6,%7}, {%8,%9}, {%0,%1,%2,%3};"
        : "+f"(c[0]), "+f"(c[1]), "+f"(c[2]), "+f"(c[3])
        : "r"(a[0]), "r"(a[1]), "r"(a[2]), "r"(a[3]), "r"(b0), "r"(b1));
}
__device__ __forceinline__ void ldmx4(uint32_t& r0, uint32_t& r1, uint32_t& r2, uint32_t& r3,
                                      uint32_t addr){
    asm volatile("ldmatrix.sync.aligned.m8n8.x4.shared.b16 {%0,%1,%2,%3}, [%4];"
                 : "=r"(r0), "=r"(r1), "=r"(r2), "=r"(r3) : "r"(addr));
}
__device__ __forceinline__ uint32_t smem_u32(const void* p){
    return (uint32_t)__cvta_generic_to_shared(p);
}
__device__ __forceinline__ void cp_async16(uint32_t sdst, const void* gsrc, int srcsize){
    asm volatile("cp.async.cg.shared.global [%0], [%1], 16, %2;"
                 :: "r"(sdst), "l"(gsrc), "r"(srcsize) : "memory");
}
#define CP_COMMIT() asm volatile("cp.async.commit_group;" ::: "memory")
#define CP_WAIT(n)  asm volatile("cp.async.wait_group %0;" :: "n"(n) : "memory")

// ---------------- weight padding -> packed e4m3 quads ----------------
template<int MPAD, int KPAD>
__global__ void prep_kernel(const float* __restrict__ W, const float* __restrict__ b,
                            uint32_t* __restrict__ Wf, float* __restrict__ bp){
    int idx = blockIdx.x * blockDim.x + threadIdx.x;
    constexpr int K4 = KPAD / 4;
    if (idx < MPAD * K4){
        int m = idx / K4, kq = idx % K4;
        float w[4];
#pragma unroll
        for (int j = 0; j < 4; j++){
            int k = 4 * kq + j;
            w[j] = (m >= 1 && k >= 1) ? W[(m - 1) * (KPAD - 1) + (k - 1)] : 0.0f;
        }
        Wf[idx] = f8pack4(w[0], w[1], w[2], w[3]);
    }
    if (idx < MPAD) bp[idx] = (idx >= 1) ? b[idx - 1] : 0.0f;
}

// ---------------- log_map_zero(x) -> u0b, accb (packed f16x2) ----------------
__global__ void lmap0_kernel(const float* __restrict__ x){
    int warp = (blockIdx.x * blockDim.x + threadIdx.x) >> 5;
    if (warp >= NNODES) return;
    int lane = threadIdx.x & 31;
    float4 a = ((const float4*)x)[(size_t)warp * 32 + lane];
    float y0 = __shfl_sync(0xffffffffu, a.x, 0);
    float s = a.x*a.x + a.y*a.y + a.z*a.z + a.w*a.w;
    if (lane == 0) s = a.y*a.y + a.z*a.z + a.w*a.w;
    float S = warpSum(s);
    float dist = arcosh_cl(y0 + EPSF);
    float g = dist / sqrtf(S + EPSF);
    float ux = (lane == 0) ? 0.0f : g * a.x;
    uint2 h;
    h.x = hpack2(ux, g * a.y);
    h.y = hpack2(g * a.z, g * a.w);
    ((uint2*)g_u0b )[(size_t)warp * 32 + lane] = h;
    ((uint2*)g_accb)[(size_t)warp * 32 + lane] = h;
}

// ---------------- segment_sum via vector f16x2 red.global (half-warp/edge) ----------------
__global__ void scatter_kernel(const int* __restrict__ ei){
    int e = (blockIdx.x * blockDim.x + threadIdx.x) >> 4;
    if (e >= NEDGES) return;
    int l16 = threadIdx.x & 15;
    int src = ei[e];
    int dst = ei[NEDGES + e];
    uint4 v = ((const uint4*)g_u0b)[(size_t)src * 16 + l16];
    uint32_t* addr = g_accb + (size_t)dst * 64 + l16 * 4;
    asm volatile("red.global.add.noftz.v4.f16x2 [%0], {%1,%2,%3,%4};"
                 :: "l"(addr), "r"(v.x), "r"(v.y), "r"(v.z), "r"(v.w) : "memory");
}

// ---------------- log_map(exp_map(acc)) -> A plane fp8 (K=128) ----------------
__global__ void manpre_kernel(){
    int warp = (blockIdx.x * blockDim.x + threadIdx.x) >> 5;
    if (warp >= NNODES) return;
    int lane = threadIdx.x & 31;
    uint2 p = ((const uint2*)g_accb)[(size_t)warp * 32 + lane];
    float ax, ay, az, aw;
    hunpack2(p.x, ax, ay);
    hunpack2(p.y, az, aw);
    float s = ax*ax + ay*ay + az*az + aw*aw;
    float S = warpSum(s);
    float n = sqrtf(fmaxf(S + EPSF, 1e-6f));
    float f = sinhf(fminf(n, 50.0f)) / n;
    float fS = f * f * S;
    float first = sqrtf(1.0f + fS);
    float dist = arcosh_cl(first + EPSF);
    float g = dist / sqrtf(fS + EPSF) * f;
    g_A8[(size_t)warp * 32 + lane] = f8pack4(g*ax, g*ay, g*az, g*aw);
}

// ---------------- post-GEMM chain (f16 in) -> fp8 A plane ----------------
template<int MP>
__global__ void rowpost_kernel(const uint32_t* __restrict__ V, uint32_t* __restrict__ U8){
    int warp = (blockIdx.x * blockDim.x + threadIdx.x) >> 5;
    if (warp >= NNODES) return;
    int lane = threadIdx.x & 31;
    constexpr int PL = MP / 128;
    const uint2* vr = (const uint2*)(V + (size_t)warp * (MP / 2));
    float a[PL][4];
    float s = 0.0f;
#pragma unroll
    for (int i = 0; i < PL; i++){
        uint2 p = vr[i * 32 + lane];
        hunpack2(p.x, a[i][0], a[i][1]);
        hunpack2(p.y, a[i][2], a[i][3]);
        s += a[i][0]*a[i][0] + a[i][1]*a[i][1] + a[i][2]*a[i][2] + a[i][3]*a[i][3];
    }
    float S = warpSum(s);
    float n = sqrtf(fmaxf(S + EPSF, 1e-6f));
    float f = sinhf(fminf(n, 50.0f)) / n;
    float fS = f * f * S;
    float first = sqrtf(1.0f + fS);
    float dist = arcosh_cl(first + EPSF);
    float g1 = dist / sqrtf(fS + EPSF) * f;
    float s2 = 0.0f;
#pragma unroll
    for (int i = 0; i < PL; i++){
#pragma unroll
        for (int j = 0; j < 4; j++){
            a[i][j] = fmaxf(g1 * a[i][j], 0.0f);
            s2 += a[i][j] * a[i][j];
        }
    }
    float S2 = warpSum(s2);
    float n2 = sqrtf(fmaxf(S2 + EPSF, 1e-6f));
    float f2 = sinhf(fminf(n2, 50.0f)) / n2;
    float f2S = f2 * f2 * S2;
    float first2 = sqrtf(1.0f + f2S);
    float dist2 = arcosh_cl(first2 + EPSF);
    float g2 = dist2 / sqrtf(f2S + EPSF) * f2;
#pragma unroll
    for (int i = 0; i < PL; i++){
        U8[(size_t)warp * (MP / 4) + i * 32 + lane] =
            f8pack4(g2*a[i][0], g2*a[i][1], g2*a[i][2], g2*a[i][3]);
    }
}

// ---------------- final rowpost (MP=384, f16 in) -> packed f16 ht ----------------
__global__ void rowpost_final_kernel(const uint32_t* __restrict__ V, uint32_t* __restrict__ Ub){
    int warp = (blockIdx.x * blockDim.x + threadIdx.x) >> 5;
    if (warp >= NNODES) return;
    int lane = threadIdx.x & 31;
    const uint2* vr = (const uint2*)(V + (size_t)warp * 192);
    float a[3][4];
    float s = 0.0f;
#pragma unroll
    for (int i = 0; i < 3; i++){
        uint2 p = vr[i * 32 + lane];
        hunpack2(p.x, a[i][0], a[i][1]);
        hunpack2(p.y, a[i][2], a[i][3]);
        s += a[i][0]*a[i][0] + a[i][1]*a[i][1] + a[i][2]*a[i][2] + a[i][3]*a[i][3];
    }
    float S = warpSum(s);
    float n = sqrtf(fmaxf(S + EPSF, 1e-6f));
    float f = sinhf(fminf(n, 50.0f)) / n;
    float fS = f * f * S;
    float first = sqrtf(1.0f + fS);
    float dist = arcosh_cl(first + EPSF);
    float g1 = dist / sqrtf(fS + EPSF) * f;
    float s2 = 0.0f;
#pragma unroll
    for (int i = 0; i < 3; i++){
#pragma unroll
        for (int j = 0; j < 4; j++){
            a[i][j] = fmaxf(g1 * a[i][j], 0.0f);
            s2 += a[i][j] * a[i][j];
        }
    }
    float S2 = warpSum(s2);
    float n2 = sqrtf(fmaxf(S2 + EPSF, 1e-6f));
    float f2 = sinhf(fminf(n2, 50.0f)) / n2;
    float f2S = f2 * f2 * S2;
    float first2 = sqrtf(1.0f + f2S);
    float dist2 = arcosh_cl(first2 + EPSF);
    float g2 = dist2 / sqrtf(f2S + EPSF) * f2;
#pragma unroll
    for (int i = 0; i < 3; i++){
        uint2 h;
        h.x = hpack2(g2*a[i][0], g2*a[i][1]);
        h.y = hpack2(g2*a[i][2], g2*a[i][3]);
        ((uint2*)Ub)[(size_t)warp * 96 + i * 32 + lane] = h;
    }
}

// ---------------- cp.async double-buffered e4m3 GEMM with ldmatrix ----------------
// A fp8, W fp8. C = A.W^T + bias (fp32 accum), stored packed f16x2.
// 256 thr (8 warps, 2m x 4n); per-warp 64x32; K-chunks of 32 elems (32 B = 8 u32).
#define ST2 12
static constexpr int STG_U32 = 2 * 128 * ST2;          // A, W tiles
static constexpr int MMA_SMEM = 2 * STG_U32 * 4;       // 24576 B

template<int K, int MOUT>
__global__ void __launch_bounds__(256, 2) mma_gemm(
        const uint32_t* __restrict__ A8, const uint32_t* __restrict__ Wf,
        const float* __restrict__ bias, uint32_t* __restrict__ C){
    extern __shared__ uint32_t smu[];
    int tid = threadIdx.x, lane = tid & 31, wid = tid >> 5;
    int brow = blockIdx.y * 128, bcol = blockIdx.x * 128;
    int mw = wid & 1, nw = wid >> 1;
    int gid = lane >> 2, tig = lane & 3;
    constexpr int NC = K / 32;       // chunks of 32 fp8 elems
    constexpr int K4 = K / 4;        // global row stride in u32

    auto load_stage = [&](int s, int kc){
        uint32_t* base = smu + s * STG_U32;
        uint32_t sA = smem_u32(base);
        uint32_t sW = smem_u32(base + 128 * ST2);
        int k0 = kc * 8;             // u32 offset of chunk
        int r = tid >> 1;
        int c4 = (tid & 1) << 2;     // 0 or 4 u32 (16B halves)
        uint32_t soff = (uint32_t)(r * ST2 + c4) * 4u;
        int gr = brow + r;
        cp_async16(sA + soff, A8 + (size_t)gr * K4 + k0 + c4, (gr < NNODES) ? 16 : 0);
        cp_async16(sW + soff, Wf + (size_t)(bcol + r) * K4 + k0 + c4, 16);
        CP_COMMIT();
    };

    // ldmatrix byte offsets (16-bit-unit view identical to fp16 k16 layout)
    uint32_t a_off = (uint32_t)((mw * 64 + (lane & 15)) * ST2 + (lane >> 4) * 4) * 4u;
    int wsn = (lane >> 4) & 1;
    int wkh = (lane >> 3) & 1;
    uint32_t w_off[2];
#pragma unroll
    for (int p = 0; p < 2; p++)
        w_off[p] = (uint32_t)((nw * 32 + p * 16 + wsn * 8 + (lane & 7)) * ST2 + wkh * 4) * 4u;

    float acc[4][4][4];
#pragma unroll
    for (int i = 0; i < 4; i++)
#pragma unroll
        for (int j = 0; j < 4; j++)
#pragma unroll
            for (int l = 0; l < 4; l++) acc[i][j][l] = 0.0f;

    load_stage(0, 0);
    if (NC > 1) load_stage(1, 1);

    uint32_t sbase = smem_u32(smu);

    for (int kc = 0; kc < NC; kc++){
        int buf = kc & 1;
        if (kc + 1 < NC) { CP_WAIT(1); } else { CP_WAIT(0); }
        __syncthreads();
        uint32_t sA = sbase + (uint32_t)(buf * STG_U32) * 4u;
        uint32_t sW = sA + 128 * ST2 * 4u;
        uint32_t ah[4][4];
#pragma unroll
        for (int sm2 = 0; sm2 < 4; sm2++)
            ldmx4(ah[sm2][0], ah[sm2][1], ah[sm2][2], ah[sm2][3],
                  sA + a_off + (uint32_t)(sm2 * 16 * ST2) * 4u);
        uint32_t bh0[4], bh1[4];
#pragma unroll
        for (int p = 0; p < 2; p++)
            ldmx4(bh0[2*p], bh1[2*p], bh0[2*p+1], bh1[2*p+1], sW + w_off[p]);
#pragma unroll
        for (int sn = 0; sn < 4; sn++){
#pragma unroll
            for (int sm2 = 0; sm2 < 4; sm2++)
                mma_f8(acc[sm2][sn], ah[sm2], bh0[sn], bh1[sn]);
        }
        __syncthreads();
        if (kc + 2 < NC) load_stage(buf, kc + 2);
    }

#pragma unroll
    for (int sm2 = 0; sm2 < 4; sm2++){
#pragma unroll
        for (int sn = 0; sn < 4; sn++){
            int row = brow + mw * 64 + sm2 * 16 + gid;
            int col = bcol + nw * 32 + sn * 8 + tig * 2;
            float2 bb = *(const float2*)(bias + col);
            if (row < NNODES){
                C[(size_t)row * (MOUT/2) + (col >> 1)] =
                    hpack2(acc[sm2][sn][0] + bb.x, acc[sm2][sn][1] + bb.y);
            }
            if (row + 8 < NNODES){
                C[(size_t)(row + 8) * (MOUT/2) + (col >> 1)] =
                    hpack2(acc[sm2][sn][2] + bb.x, acc[sm2][sn][3] + bb.y);
            }
        }
    }
}

// ---------------- mean over nodes (f16 in, fp32 sums) ----------------
__global__ void zero384_kernel(){ g_sums[threadIdx.x] = 0.0f; }

__global__ void mean_kernel(const uint32_t* __restrict__ U){
    int t = threadIdx.x;              // 192 threads, one u32 column each
    int start = blockIdx.x * 250;
    int end = start + 250;
    float s0 = 0.0f, s1 = 0.0f;
    for (int nn = start; nn < end; nn++){
        uint32_t p = U[(size_t)nn * 192 + t];
        float lo, hi;
        hunpack2(p, lo, hi);
        s0 += lo; s1 += hi;
    }
    atomicAdd(&g_sums[2 * t],     s0);
    atomicAdd(&g_sums[2 * t + 1], s1);
}

// ---------------- final classifier head ----------------
__global__ void classify_kernel(const float* __restrict__ Wc, const float* __restrict__ bc,
                                float* __restrict__ out){
    __shared__ float sh_hm[384];
    __shared__ float sh_warp[16];
    __shared__ float sh_mx[10];
    __shared__ float sh_factor;
    int t = threadIdx.x, lane = t & 31, wid = t >> 5;
    float v = 0.0f;
    if (t < 384) v = g_sums[t] * (1.0f / (float)NNODES);
    if (t == 0) v = 0.0f;
    if (t < 384) sh_hm[t] = v;
    float s = warpSum(v * v);
    if (lane == 0) sh_warp[wid] = s;
    __syncthreads();
    if (t == 0){
        float S = 0.0f;
        for (int i = 0; i < 16; i++) S += sh_warp[i];
        float nrm = sqrtf(S + EPSF);
        float dist = arcosh_cl(0.0f + EPSF);
        sh_factor = dist / nrm;
    }
    __syncthreads();
    float factor = sh_factor;
    if (wid < 9){
        float d = 0.0f;
        for (int j = lane; j < 383; j += 32) d += sh_hm[j + 1] * factor * Wc[wid * 383 + j];
        d = warpSum(d);
        if (lane == 0) sh_mx[wid + 1] = d + bc[wid];
    }
    if (t == 0) sh_mx[0] = 0.0f;
    __syncthreads();
    if (t == 0){
        float mx[10];
#pragma unroll
        for (int i = 0; i < 10; i++) mx[i] = sh_mx[i];
        float S = 0.0f;
        for (int i = 1; i < 10; i++) S += mx[i] * mx[i];
        float n = sqrtf(fmaxf(S + EPSF, 1e-6f));
        float f = sinhf(fminf(n, 50.0f)) / n;
        float fS = f * f * S;
        float hc[10];
        bool cond = (S == 0.0f);
        if (cond){
            for (int i = 0; i < 10; i++) hc[i] = 0.0f;
        } else {
            hc[0] = sqrtf(1.0f + fS);
            for (int i = 1; i < 10; i++) hc[i] = f * mx[i];
        }
        for (int i = 0; i < 10; i++) out[i] = hc[i];
        float x0c = fmaxf(hc[0] + EPSF, 1.0f + EPSF);
        float dd = logf(x0c + sqrtf(x0c * x0c - 1.0f));
        float tn = 0.0f;
        for (int i = 1; i < 10; i++) tn += hc[i] * hc[i];
        float nr = sqrtf(tn + EPSF);
        float gf = dd / nr;
        float lt[10]; lt[0] = 0.0f;
        for (int i = 1; i < 10; i++) lt[i] = gf * hc[i];
        float mmax = lt[0];
        for (int i = 1; i < 10; i++) mmax = fmaxf(mmax, lt[i]);
        float e[10], se = 0.0f;
        for (int i = 0; i < 10; i++){ e[i] = expf(lt[i] - mmax); se += e[i]; }
        float p[10];
        for (int i = 0; i < 10; i++) p[i] = e[i] / se;
        p[0] = 0.0f;
        float S3 = 0.0f;
        for (int i = 1; i < 10; i++) S3 += p[i] * p[i];
        float n3 = sqrtf(fmaxf(S3 + EPSF, 1e-6f));
        float f3 = sinhf(fminf(n3, 50.0f)) / n3;
        float f3S = f3 * f3 * S3;
        out[10] = sqrtf(1.0f + f3S);
        for (int i = 1; i < 10; i++) out[10 + i] = f3 * p[i];
    }
}

// ---------------- launch ----------------
extern "C" void kernel_launch(void* const* d_in, const int* in_sizes, int n_in,
                              void* d_out, int out_size){
    const float* x  = (const float*)d_in[0];
    const int*   ei = (const int*)  d_in[1];
    const float* W0 = (const float*)d_in[2];
    const float* b0 = (const float*)d_in[3];
    const float* W1 = (const float*)d_in[4];
    const float* b1 = (const float*)d_in[5];
    const float* W2 = (const float*)d_in[6];
    const float* b2 = (const float*)d_in[7];
    const float* Wc = (const float*)d_in[8];
    const float* bc = (const float*)d_in[9];
    float* out = (float*)d_out;

    uint32_t *pW0f,*pW1f,*pW2f,*pA8,*pV,*pBb;
    float *pbp0,*pbp1,*pbp2;
    cudaGetSymbolAddress((void**)&pW0f, g_W0f);
    cudaGetSymbolAddress((void**)&pW1f, g_W1f);
    cudaGetSymbolAddress((void**)&pW2f, g_W2f);
    cudaGetSymbolAddress((void**)&pbp0, g_bp0);
    cudaGetSymbolAddress((void**)&pbp1, g_bp1);
    cudaGetSymbolAddress((void**)&pbp2, g_bp2);
    cudaGetSymbolAddress((void**)&pA8,  g_A8);
    cudaGetSymbolAddress((void**)&pV,   g_v);
    cudaGetSymbolAddress((void**)&pBb,  g_bufBb);

    cudaFuncSetAttribute(mma_gemm<128,128>, cudaFuncAttributeMaxDynamicSharedMemorySize, MMA_SMEM);
    cudaFuncSetAttribute(mma_gemm<128,256>, cudaFuncAttributeMaxDynamicSharedMemorySize, MMA_SMEM);
    cudaFuncSetAttribute(mma_gemm<256,384>, cudaFuncAttributeMaxDynamicSharedMemorySize, MMA_SMEM);

    prep_kernel<128,128><<<(128*32 + 255)/256, 256>>>(W0, b0, pW0f, pbp0);
    prep_kernel<256,128><<<(256*32 + 255)/256, 256>>>(W1, b1, pW1f, pbp1);
    prep_kernel<384,256><<<(384*64 + 255)/256, 256>>>(W2, b2, pW2f, pbp2);

    const int RB = (NNODES + 7) / 8;
    const int NT = (NNODES + 127) / 128;   // 391 row tiles

    lmap0_kernel<<<RB, 256>>>(x);
    scatter_kernel<<<(NEDGES + 15)/16, 256>>>(ei);
    manpre_kernel<<<RB, 256>>>();

    mma_gemm<128,128><<<dim3(1, NT), 256, MMA_SMEM>>>(pA8, pW0f, pbp0, pV);
    rowpost_kernel<128><<<RB, 256>>>(pV, pA8);
    mma_gemm<128,256><<<dim3(2, NT), 256, MMA_SMEM>>>(pA8, pW1f, pbp1, pV);
    rowpost_kernel<256><<<RB, 256>>>(pV, pA8);
    mma_gemm<256,384><<<dim3(3, NT), 256, MMA_SMEM>>>(pA8, pW2f, pbp2, pV);
    rowpost_final_kernel<<<RB, 256>>>(pV, pBb);

    zero384_kernel<<<1, 384>>>();
    mean_kernel<<<200, 192>>>(pBb);
    classify_kernel<<<1, 512>>>(Wc, bc, out);
}